// round 16
// baseline (speedup 1.0000x reference)
#include <cuda_runtime.h>

#define CC   2
#define HH   200
#define WW   200
#define NN   200
#define HWN  (HH*WW*NN)
#define N4   (NN/4)                     // 50 float4 groups per (h,w)
#define NGROUPS (HH*WW*N4)              // 2,000,000
#define BLOCK 512
#define GRID_CTAS 592                   // 148 SMs x 4 CTAs x 512thr: one wave
#define NTHREADS (GRID_CTAS*BLOCK)      // 303,104 (same as R10/R15)

// Factorized per-axis cell tables (int8):
//   g_cx[w*NN + n] = cx in {0,1}, or -1 if x outside [x1,x2]
//   g_cy[h*NN + n] = cy in {0,1}, or -1 if y outside [y1,y2]
__device__ signed char g_cx[WW * NN];
__device__ signed char g_cy[HH * NN];

__global__ void prep_kernel(const float* __restrict__ rois) {
    int idx = blockIdx.x * blockDim.x + threadIdx.x;   // [0, 2*200*200)
    if (idx < 2 * WW * NN) {
        int axis = idx / (WW * NN);     // 0 = x, 1 = y
        int rem  = idx % (WW * NN);
        int p    = rem / NN;            // pixel coord (w or h)
        int n    = rem % NN;

        float lo = rois[4 * n + (axis ? 1 : 0)];   // x1 or y1
        float hi = rois[4 * n + (axis ? 3 : 2)];   // x2 or y2
        float cl = fmaxf(hi - lo, 1.0f);
        // double-precision reciprocal so (p-lo)*s tracks fp32 CC*(p-lo)/cl to ~1 ulp
        float s  = (float)((double)CC / (double)cl);

        float pf = (float)p;
        signed char v = -1;
        if (pf >= lo && pf <= hi) {
            int c = (int)floorf((pf - lo) * s);
            c = min(max(c, 0), CC - 1);
            v = (signed char)c;
        }
        if (axis == 0) g_cx[p * NN + n] = v;
        else           g_cy[p * NN + n] = v;
    }
    // PDL: allow the dependent crop kernel to begin early.
    cudaTriggerProgrammaticLaunchCompletion();
}

__device__ __forceinline__ void do_group(int gi,
                                         const float* __restrict__ data,
                                         float* __restrict__ out) {
    int n4 = gi % N4;           // group of 4 consecutive n
    int hw = gi / N4;           // h*WW + w
    int w  = hw % WW;
    int h  = hw / WW;

    int base = hw * NN + n4 * 4;   // 16B aligned

    char4 cx4 = *reinterpret_cast<const char4*>(g_cx + w * NN + n4 * 4);
    char4 cy4 = *reinterpret_cast<const char4*>(g_cy + h * NN + n4 * 4);

    signed char cxs[4] = {cx4.x, cx4.y, cx4.z, cx4.w};
    signed char cys[4] = {cy4.x, cy4.y, cy4.z, cy4.w};

    float v[4];
    #pragma unroll
    for (int i = 0; i < 4; i++) {
        int cx = cxs[i];
        int cy = cys[i];
        float val = 0.0f;
        if ((cx | cy) >= 0) {
            int cell = cy * CC + cx;
            val = __ldg(data + (size_t)cell * HWN + base + i);
        }
        v[i] = val;
    }

    *reinterpret_cast<float4*>(out + base) = make_float4(v[0], v[1], v[2], v[3]);
}

// Persistent single-wave kernel (proven body), 512-thread CTAs: half the
// CTA scheduling events, identical warp-level access pattern.
__global__ void __launch_bounds__(BLOCK)
crop_split_kernel(const float* __restrict__ data, float* __restrict__ out) {
    int t = blockIdx.x * BLOCK + threadIdx.x;

    // Wait for prep's table writes (PDL consumer side).
    cudaGridDependencySynchronize();

    // NGROUPS / NTHREADS = 6.598 -> 6 full strided passes + partial 7th
    int gi = t;
    #pragma unroll 2
    for (int it = 0; it < 6; it++) {
        do_group(gi, data, out);
        gi += NTHREADS;
    }
    if (gi < NGROUPS)
        do_group(gi, data, out);
}

extern "C" void kernel_launch(void* const* d_in, const int* in_sizes, int n_in,
                              void* d_out, int out_size) {
    const float* data = (const float*)d_in[0];   // (4, H, W, N) fp32
    const float* rois = (const float*)d_in[1];   // (N, 4) fp32
    float* out = (float*)d_out;                  // (H, W, N) fp32

    int prep_elems = 2 * WW * NN;                // 80000
    prep_kernel<<<(prep_elems + 255) / 256, 256>>>(rois);

    // Launch crop with programmatic stream serialization (PDL).
    cudaLaunchConfig_t cfg = {};
    cfg.gridDim  = dim3(GRID_CTAS, 1, 1);
    cfg.blockDim = dim3(BLOCK, 1, 1);
    cudaLaunchAttribute attr[1];
    attr[0].id = cudaLaunchAttributeProgrammaticStreamSerialization;
    attr[0].val.programmaticStreamSerializationAllowed = 1;
    cfg.attrs = attr;
    cfg.numAttrs = 1;
    cudaLaunchKernelEx(&cfg, crop_split_kernel, data, out);
}

// round 17
// speedup vs baseline: 1.3898x; 1.3898x over previous
#include <cuda_runtime.h>

#define CC   2
#define HH   200
#define WW   200
#define NN   200
#define HWN  (HH*WW*NN)
#define N4   (NN/4)                     // 50 float4 groups per (h,w)
#define NGROUPS (HH*WW*N4)              // 2,000,000
#define GRID_CTAS 1184                  // 148 SMs x 8 CTAs: exactly one wave
#define NTHREADS (GRID_CTAS*256)        // 303,104

// Factorized per-axis cell tables (int8):
//   g_cx[w*NN + n] = cx in {0,1}, or -1 if x outside [x1,x2]
//   g_cy[h*NN + n] = cy in {0,1}, or -1 if y outside [y1,y2]
__device__ signed char g_cx[WW * NN];
__device__ signed char g_cy[HH * NN];

__global__ void prep_kernel(const float* __restrict__ rois) {
    int idx = blockIdx.x * blockDim.x + threadIdx.x;   // [0, 2*200*200)
    if (idx < 2 * WW * NN) {
        int axis = idx / (WW * NN);     // 0 = x, 1 = y
        int rem  = idx % (WW * NN);
        int p    = rem / NN;            // pixel coord (w or h)
        int n    = rem % NN;

        float lo = rois[4 * n + (axis ? 1 : 0)];   // x1 or y1
        float hi = rois[4 * n + (axis ? 3 : 2)];   // x2 or y2
        float cl = fmaxf(hi - lo, 1.0f);
        // double-precision reciprocal so (p-lo)*s tracks fp32 CC*(p-lo)/cl to ~1 ulp
        float s  = (float)((double)CC / (double)cl);

        float pf = (float)p;
        signed char v = -1;
        if (pf >= lo && pf <= hi) {
            int c = (int)floorf((pf - lo) * s);
            c = min(max(c, 0), CC - 1);
            v = (signed char)c;
        }
        if (axis == 0) g_cx[p * NN + n] = v;
        else           g_cy[p * NN + n] = v;
    }
    // PDL: allow the dependent crop kernel to begin; its table reads are
    // gated by cudaGridDependencySynchronize() on the consumer side.
    cudaTriggerProgrammaticLaunchCompletion();
}

__device__ __forceinline__ void do_group(int gi,
                                         const float* __restrict__ data,
                                         float* __restrict__ out) {
    int n4 = gi % N4;           // group of 4 consecutive n
    int hw = gi / N4;           // h*WW + w
    int w  = hw % WW;
    int h  = hw / WW;

    int base = hw * NN + n4 * 4;   // 16B aligned

    char4 cx4 = *reinterpret_cast<const char4*>(g_cx + w * NN + n4 * 4);
    char4 cy4 = *reinterpret_cast<const char4*>(g_cy + h * NN + n4 * 4);

    signed char cxs[4] = {cx4.x, cx4.y, cx4.z, cx4.w};
    signed char cys[4] = {cy4.x, cy4.y, cy4.z, cy4.w};

    float v[4];
    #pragma unroll
    for (int i = 0; i < 4; i++) {
        int cx = cxs[i];
        int cy = cys[i];
        float val = 0.0f;
        if ((cx | cy) >= 0) {
            int cell = cy * CC + cx;
            val = __ldg(data + (size_t)cell * HWN + base + i);
        }
        v[i] = val;
    }

    *reinterpret_cast<float4*>(out + base) = make_float4(v[0], v[1], v[2], v[3]);
}

// Persistent single-wave kernel: 1184 CTAs x 256 threads grid-stride over
// the 2M groups. No wave transitions; unroll 2 keeps two groups' loads in
// flight per thread. Launched via PDL to overlap with prep's tail.
__global__ void __launch_bounds__(256)
crop_split_kernel(const float* __restrict__ data, float* __restrict__ out) {
    int t = blockIdx.x * 256 + threadIdx.x;

    // Wait for prep's table writes (PDL consumer side).
    cudaGridDependencySynchronize();

    // NGROUPS / NTHREADS = 6.598 -> 6 full strided passes + partial 7th
    int gi = t;
    #pragma unroll 2
    for (int it = 0; it < 6; it++) {
        do_group(gi, data, out);
        gi += NTHREADS;
    }
    if (gi < NGROUPS)
        do_group(gi, data, out);
}

extern "C" void kernel_launch(void* const* d_in, const int* in_sizes, int n_in,
                              void* d_out, int out_size) {
    const float* data = (const float*)d_in[0];   // (4, H, W, N) fp32
    const float* rois = (const float*)d_in[1];   // (N, 4) fp32
    float* out = (float*)d_out;                  // (H, W, N) fp32

    int prep_elems = 2 * WW * NN;                // 80000
    prep_kernel<<<(prep_elems + 255) / 256, 256>>>(rois);

    // Launch crop with programmatic stream serialization (PDL).
    cudaLaunchConfig_t cfg = {};
    cfg.gridDim  = dim3(GRID_CTAS, 1, 1);
    cfg.blockDim = dim3(256, 1, 1);
    cudaLaunchAttribute attr[1];
    attr[0].id = cudaLaunchAttributeProgrammaticStreamSerialization;
    attr[0].val.programmaticStreamSerializationAllowed = 1;
    cfg.attrs = attr;
    cfg.numAttrs = 1;
    cudaLaunchKernelEx(&cfg, crop_split_kernel, data, out);
}